// round 5
// baseline (speedup 1.0000x reference)
#include <cuda_runtime.h>
#include <cuda_fp16.h>
#include <stdint.h>

// ===================== problem dims =====================
// B=8, T=1M, V=257, E=8, C=128, K=S=512, N=64 patches
// GEMM: M=16384 windows, N=256 (c1/c2 interleaved in 16-row groups), K=4096
// CTA: 256 windows x 128 N-cols, 512 threads / 16 warps (4 Mwarps x 4 Nwarps)
// Warp tile 64x32, acc = 64 fp32 regs/thread. K-stage = 128 halves (16 byte-positions).
// Grid = 64 M-tiles x 2 N-halves = 128 CTAs.

#define THREADS    512
#define NITER      32            // K stages of 128 halves (= 16 byte positions)

// smem offsets from 1024-aligned base (2-stage pipeline)
#define A_BYTES    65536         // 256 rows x 256B
#define B_BYTES    32768         // 128 rows x 256B (one N-half)
#define OFF_A      0                         // 2 buffers
#define OFF_B      (2 * A_BYTES)             // 131072, 2 buffers
#define OFF_EMB    (OFF_B + 2 * B_BYTES)     // 196608; emb fp16: 257 * 16B
#define SMEM_ALLOC (OFF_EMB + 4128 + 1024)   // 201760

// packed weights: [32 K-stages][256 rows x 256B, pre-swizzled] = 2 MB
__device__ __align__(16) unsigned char g_Bpack[32 * 65536];

// ===================== helpers =====================
static __device__ __forceinline__ uint32_t smem_u32(const void* p) {
    uint32_t a;
    asm("{ .reg .u64 t; cvta.to.shared.u64 t, %1; cvt.u32.u64 %0, t; }" : "=r"(a) : "l"(p));
    return a;
}

#define STS128(addr, r0, r1, r2, r3) \
    asm volatile("st.shared.v4.b32 [%0], {%1,%2,%3,%4};" :: "r"(addr), "r"(r0), "r"(r1), "r"(r2), "r"(r3) : "memory")
#define LDS128(r0, r1, r2, r3, addr) \
    asm volatile("ld.shared.v4.b32 {%0,%1,%2,%3}, [%4];" : "=r"(r0), "=r"(r1), "=r"(r2), "=r"(r3) : "r"(addr))

#define LDSM4(r0, r1, r2, r3, addr) \
    asm volatile("ldmatrix.sync.aligned.m8n8.x4.shared.b16 {%0,%1,%2,%3}, [%4];" \
                 : "=r"(r0), "=r"(r1), "=r"(r2), "=r"(r3) : "r"(addr))

#define MMA16816(d, a0, a1, a2, a3, b0, b1) \
    asm volatile("mma.sync.aligned.m16n8k16.row.col.f32.f16.f16.f32 " \
                 "{%0,%1,%2,%3}, {%4,%5,%6,%7}, {%8,%9}, {%0,%1,%2,%3};" \
                 : "+f"((d)[0]), "+f"((d)[1]), "+f"((d)[2]), "+f"((d)[3]) \
                 : "r"(a0), "r"(a1), "r"(a2), "r"(a3), "r"(b0), "r"(b1))

#define CP_ASYNC16(dst, src) \
    asm volatile("cp.async.cg.shared.global [%0], [%1], 16;" :: "r"(dst), "l"(src) : "memory")
#define CP_COMMIT()  asm volatile("cp.async.commit_group;" ::: "memory")
#define CP_WAIT0()   asm volatile("cp.async.wait_group 0;" ::: "memory")

// ===================== prep: pack weights fp16, K-major, pre-swizzled =====================
// Stage layout: 256 rows x 256B; unit cu (0..15) of row stored at
//   row*256 + (((cu&7) ^ (row&7))<<4) + ((cu>>3)<<7).
// Unit cu holds e=0..7 (fp16) of byte position k = it*16 + cu.
// Row n: h=n>>5, s=(n>>4)&1, r=n&15; s=0 -> w1, s=1 -> w2; channel = h*16 + r.
__global__ void pack_weights(const float* __restrict__ w1, const float* __restrict__ w2) {
    uint32_t t = blockIdx.x * 256u + threadIdx.x;   // 0..131071, one 16B unit each
    uint32_t it = t >> 12;                          // 4096 units per 64KB stage
    uint32_t swoff = (t & 4095u) << 4;              // byte offset inside stage
    uint32_t row = swoff >> 8;
    uint32_t inrow = swoff & 255u;
    uint32_t cu = ((((inrow >> 4) & 7u) ^ (row & 7u))) | ((inrow >> 7) << 3);
    uint32_t k = it * 16u + cu;                     // byte position 0..511
    uint32_t h = row >> 5, s_ = (row >> 4) & 1u, r = row & 15u;
    const float* w = s_ ? w2 : w1;
    const float* s = w + (h * 16u + r) * 4096u + k; // + e*512
    __half2 h0 = __floats2half2_rn(s[0],    s[512]);
    __half2 h1 = __floats2half2_rn(s[1024], s[1536]);
    __half2 h2 = __floats2half2_rn(s[2048], s[2560]);
    __half2 h3 = __floats2half2_rn(s[3072], s[3584]);
    uint4 v;
    v.x = *reinterpret_cast<uint32_t*>(&h0);
    v.y = *reinterpret_cast<uint32_t*>(&h1);
    v.z = *reinterpret_cast<uint32_t*>(&h2);
    v.w = *reinterpret_cast<uint32_t*>(&h3);
    reinterpret_cast<uint4*>(g_Bpack)[t] = v;
}

// ===================== main fused kernel =====================
__global__ __launch_bounds__(THREADS, 1)
void malconv_main(const int* __restrict__ x, const float* __restrict__ emb,
                  const float* __restrict__ b1, const float* __restrict__ b2,
                  float* __restrict__ out) {
    extern __shared__ unsigned char smem_raw[];
    const uint32_t AL = (smem_u32(smem_raw) + 1023u) & ~1023u;
    const uint32_t sE = AL + OFF_EMB;

    const int tid   = threadIdx.x;
    const int wid   = tid >> 5;
    const int lane  = tid & 31;
    const int mw    = wid >> 2;            // 0..3  (64 rows each)
    const int nw    = wid & 3;             // 0..3  (32 cols each)
    const int ctam  = blockIdx.x >> 1;     // 0..63 M-tile
    const int nhalf = blockIdx.x & 1;      // 0..1  N-half
    const int m0    = ctam * 256;          // global window base

    // --- emb -> smem fp16 (16B per vocab entry: e0..e7) ---
    for (int v = tid; v < 257; v += THREADS) {
        const float4* e4 = reinterpret_cast<const float4*>(emb + v * 8);
        float4 a = e4[0], bq = e4[1];
        __half2 h0 = __floats2half2_rn(a.x, a.y);
        __half2 h1 = __floats2half2_rn(a.z, a.w);
        __half2 h2 = __floats2half2_rn(bq.x, bq.y);
        __half2 h3 = __floats2half2_rn(bq.z, bq.w);
        STS128(sE + v * 16,
               *reinterpret_cast<uint32_t*>(&h0), *reinterpret_cast<uint32_t*>(&h1),
               *reinterpret_cast<uint32_t*>(&h2), *reinterpret_cast<uint32_t*>(&h3));
    }
    __syncthreads();   // emb visible to A-build

    // --- A-build constants: thread builds row bm, units bu0..bu0+7 (stage = 16 units) ---
    const int bm  = tid >> 1;              // 0..255
    const int bu0 = (tid & 1) * 8;
    const int* xrow = x + (size_t)(m0 + bm) * 512 + bu0;
    const int bmx = bm & 7;

    // build 2 units (q0, q0+1) of this thread's row
    #define BUILD_A2(sA_, xv0_, xv1_, q0_) do {                                         \
        uint32_t e0, e1, e2, e3;                                                        \
        LDS128(e0, e1, e2, e3, sE + (uint32_t)(xv0_) * 16);                             \
        {   int cu_ = bu0 + (q0_);                                                      \
            uint32_t off_ = (uint32_t)(bm * 256 + (((cu_ & 7) ^ bmx) << 4)              \
                                       + ((cu_ >> 3) << 7));                            \
            STS128((sA_) + off_, e0, e1, e2, e3); }                                     \
        LDS128(e0, e1, e2, e3, sE + (uint32_t)(xv1_) * 16);                             \
        {   int cu_ = bu0 + (q0_) + 1;                                                  \
            uint32_t off_ = (uint32_t)(bm * 256 + (((cu_ & 7) ^ bmx) << 4)              \
                                       + ((cu_ >> 3) << 7));                            \
            STS128((sA_) + off_, e0, e1, e2, e3); }                                     \
    } while (0)

    #define ISSUE_B(stage_, buf_) do {                                                  \
        const char* src_ = (const char*)g_Bpack + (size_t)(stage_) * 65536              \
                           + (size_t)nhalf * 32768;                                     \
        uint32_t dst_ = AL + OFF_B + (buf_) * B_BYTES;                                  \
        _Pragma("unroll")                                                               \
        for (int q_ = 0; q_ < 4; ++q_)                                                  \
            CP_ASYNC16(dst_ + (tid + q_ * 512) * 16, src_ + (tid + q_ * 512) * 16);     \
        CP_COMMIT();                                                                    \
    } while (0)

    // --- prologue: B(0) async; A(0) full build; x(1) prefetch ---
    ISSUE_B(0, 0);
    {
        int4 xa = *reinterpret_cast<const int4*>(xrow + 0);
        int4 xb = *reinterpret_cast<const int4*>(xrow + 4);
        const uint32_t sA0 = AL + OFF_A;
        BUILD_A2(sA0, xa.x, xa.y, 0);
        BUILD_A2(sA0, xa.z, xa.w, 2);
        BUILD_A2(sA0, xb.x, xb.y, 4);
        BUILD_A2(sA0, xb.z, xb.w, 6);
    }
    int4 xca = *reinterpret_cast<const int4*>(xrow + 16);
    int4 xcb = *reinterpret_cast<const int4*>(xrow + 20);

    // --- per-thread ldmatrix address constants ---
    const int q4 = lane >> 3;                          // matrix index 0..3
    const int aRowBase = mw * 64 + (lane & 7) + ((q4 & 1) << 3);
    const int aCuHalf  = q4 >> 1;
    const int aXor     = aRowBase & 7;
    const int bRowBase = nw * 32 + (lane & 7) + ((lane >> 4) << 3);
    const int bCuHalf  = (lane >> 3) & 1;
    const int bXor     = bRowBase & 7;

    float acc[4][4][4];       // [mt][n8t][reg]; n8t 0,1 = c1; 2,3 = c2 (same channels)
    #pragma unroll
    for (int i = 0; i < 4; ++i)
        #pragma unroll
        for (int j = 0; j < 4; ++j)
            #pragma unroll
            for (int k = 0; k < 4; ++k) acc[i][j][k] = 0.0f;

    #define OFFA(j_) ((uint32_t)(((((j_) * 2 + aCuHalf) & 7) ^ aXor) << 4) + \
                      ((uint32_t)(((j_) * 2 + aCuHalf) >> 3) << 7))
    #define OFFB(j_) ((uint32_t)(((((j_) * 2 + bCuHalf) & 7) ^ bXor) << 4) + \
                      ((uint32_t)(((j_) * 2 + bCuHalf) >> 3) << 7))

    // --- main loop ---
    for (int it = 0; it < NITER; ++it) {
        CP_WAIT0();               // B(it) resident
        __syncthreads();          // A(it) visible; stage it-1 reads all retired

        const int bufc = it & 1;
        const uint32_t sA = AL + OFF_A + bufc * A_BYTES;
        const uint32_t sB = AL + OFF_B + bufc * B_BYTES;
        const int sNew = it + 1;
        const uint32_t sAn = AL + OFF_A + (sNew & 1) * A_BYTES;

        #pragma unroll
        for (int j = 0; j < 8; ++j) {
            // load this j's fragments
            uint32_t a[4][4];
            const uint32_t oA = OFFA(j);
            #pragma unroll
            for (int mt = 0; mt < 4; ++mt)
                LDSM4(a[mt][0], a[mt][1], a[mt][2], a[mt][3],
                      sA + (uint32_t)(aRowBase + mt * 16) * 256 + oA);
            uint32_t b0[4], b1v_[4];
            const uint32_t oB = OFFB(j);
            LDSM4(b0[0], b0[1], b0[2], b0[3], sB + (uint32_t)bRowBase * 256 + oB);
            LDSM4(b1v_[0], b1v_[1], b1v_[2], b1v_[3],
                  sB + (uint32_t)(bRowBase + 16) * 256 + oB);

            // spread next-stage work across j-steps (issues under the MMAs)
            if (sNew < NITER) {
                if (j == 0) {
                    ISSUE_B(sNew, sNew & 1);
                } else if (j == 1) { BUILD_A2(sAn, xca.x, xca.y, 0);
                } else if (j == 2) { BUILD_A2(sAn, xca.z, xca.w, 2);
                } else if (j == 3) { BUILD_A2(sAn, xcb.x, xcb.y, 4);
                } else if (j == 4) { BUILD_A2(sAn, xcb.z, xcb.w, 6);
                } else if (j == 5) {
                    if (sNew + 1 < NITER) {
                        xca = *reinterpret_cast<const int4*>(xrow + (sNew + 1) * 16);
                        xcb = *reinterpret_cast<const int4*>(xrow + (sNew + 1) * 16 + 4);
                    }
                }
            }

            // 16 MMAs
            #pragma unroll
            for (int mt = 0; mt < 4; ++mt) {
                MMA16816(acc[mt][0], a[mt][0], a[mt][1], a[mt][2], a[mt][3], b0[0], b0[1]);
                MMA16816(acc[mt][1], a[mt][0], a[mt][1], a[mt][2], a[mt][3], b0[2], b0[3]);
                MMA16816(acc[mt][2], a[mt][0], a[mt][1], a[mt][2], a[mt][3], b1v_[0], b1v_[1]);
                MMA16816(acc[mt][3], a[mt][0], a[mt][1], a[mt][2], a[mt][3], b1v_[2], b1v_[3]);
            }
        }
        if (sNew >= NITER) CP_COMMIT();
    }

    // --- epilogue: gate + per-patch max, warp-local ---
    // acc[mt][nt] nt 0,1 = c1 channels h*16 + nt*8 + 2*(lane&3)+cc; nt+2 = matching c2.
    const int h = nhalf * 4 + nw;
    float2 b1v[2], b2v[2];
    {
        const int cb = h * 16 + 2 * (lane & 3);
        #pragma unroll
        for (int nt = 0; nt < 2; ++nt) {
            b1v[nt] = __ldg(reinterpret_cast<const float2*>(b1 + cb + nt * 8));
            b2v[nt] = __ldg(reinterpret_cast<const float2*>(b2 + cb + nt * 8));
        }
    }
    const int bidx  = ctam >> 3;                       // batch
    const int pbase = (ctam & 7) * 8 + mw * 2;         // patch base within batch

    #pragma unroll
    for (int pp = 0; pp < 2; ++pp) {
        float* obase = out + (size_t)bidx * 8192 + (size_t)(pbase + pp) * 128;
        #pragma unroll
        for (int nt = 0; nt < 2; ++nt) {
            float gm[2];
            #pragma unroll
            for (int cc = 0; cc < 2; ++cc) {
                float bb1 = (cc == 0) ? b1v[nt].x : b1v[nt].y;
                float bb2 = (cc == 0) ? b2v[nt].x : b2v[nt].y;
                float g = -1e30f;
                #pragma unroll
                for (int mt = pp * 2; mt < pp * 2 + 2; ++mt) {
                    #pragma unroll
                    for (int rh = 0; rh < 2; ++rh) {
                        float c1v = acc[mt][nt][cc + rh * 2] + bb1;
                        float c2v = acc[mt][nt + 2][cc + rh * 2] + bb2;
                        float s = __expf(-c2v);
                        g = fmaxf(g, c1v * __frcp_rn(1.0f + s));
                    }
                }
                #pragma unroll
                for (int off = 4; off <= 16; off <<= 1)
                    g = fmaxf(g, __shfl_xor_sync(0xFFFFFFFFu, g, off));
                gm[cc] = g;
            }
            if ((lane >> 2) == 0) {
                const int ch = h * 16 + nt * 8 + 2 * (lane & 3);
                *reinterpret_cast<float2*>(obase + ch) = make_float2(gm[0], gm[1]);
            }
        }
    }
}

// ===================== launch =====================
extern "C" void kernel_launch(void* const* d_in, const int* in_sizes, int n_in,
                              void* d_out, int out_size) {
    const int*   x   = (const int*)d_in[0];
    const float* emb = (const float*)d_in[1];
    const float* w1  = (const float*)d_in[2];
    const float* b1  = (const float*)d_in[3];
    const float* w2  = (const float*)d_in[4];
    const float* b2  = (const float*)d_in[5];
    float* out = (float*)d_out;

    cudaFuncSetAttribute(malconv_main, cudaFuncAttributeMaxDynamicSharedMemorySize, SMEM_ALLOC);

    pack_weights<<<512, 256>>>(w1, w2);
    malconv_main<<<128, THREADS, SMEM_ALLOC>>>(x, emb, b1, b2, out);
}

// round 6
// speedup vs baseline: 1.0301x; 1.0301x over previous
#include <cuda_runtime.h>
#include <cuda_fp16.h>
#include <stdint.h>

// ===================== problem dims =====================
// B=8, T=1M, V=257, E=8, C=128, K=S=512, N=64 patches
// GEMM: M=16384 windows, N=256 (c1||c2 interleaved by 32-ch groups), K=4096
// CTA: 128 windows (4 patches, one batch), 256 threads / 8 warps (2 Mwarps x 4 Nwarps)
// Warp tile 64x64. fp16 accumulators, flushed to fp32 every 2 K-stages.

#define THREADS    256
#define NITER      32            // K stages of 128 halves (= 16 byte positions)

// smem offsets from 1024-aligned base (2-stage pipeline)
#define A_BYTES    32768         // 128 rows x 256B
#define B_BYTES    65536         // 256 rows x 256B
#define OFF_A      0                         // 2 buffers
#define OFF_B      (2 * A_BYTES)             // 65536, 2 buffers
#define OFF_EMB    (OFF_B + 2 * B_BYTES)     // 196608; emb fp16: 257 * 16B
#define SMEM_ALLOC (OFF_EMB + 4128 + 1024)   // 201760

// packed weights: [32 K-stages][256 rows x 256B, pre-swizzled] = 2 MB
__device__ __align__(16) unsigned char g_Bpack[32 * 65536];

// ===================== helpers =====================
static __device__ __forceinline__ uint32_t smem_u32(const void* p) {
    uint32_t a;
    asm("{ .reg .u64 t; cvta.to.shared.u64 t, %1; cvt.u32.u64 %0, t; }" : "=r"(a) : "l"(p));
    return a;
}

#define STS128(addr, r0, r1, r2, r3) \
    asm volatile("st.shared.v4.b32 [%0], {%1,%2,%3,%4};" :: "r"(addr), "r"(r0), "r"(r1), "r"(r2), "r"(r3) : "memory")
#define LDS128(r0, r1, r2, r3, addr) \
    asm volatile("ld.shared.v4.b32 {%0,%1,%2,%3}, [%4];" : "=r"(r0), "=r"(r1), "=r"(r2), "=r"(r3) : "r"(addr))

#define LDSM4(r0, r1, r2, r3, addr) \
    asm volatile("ldmatrix.sync.aligned.m8n8.x4.shared.b16 {%0,%1,%2,%3}, [%4];" \
                 : "=r"(r0), "=r"(r1), "=r"(r2), "=r"(r3) : "r"(addr))

// fp16-accumulator MMA: D,C = 2x b32 (4 halves) — 8 distinct src regs vs 10 for f32 acc
#define MMA16816H(d, a0, a1, a2, a3, b0, b1) \
    asm volatile("mma.sync.aligned.m16n8k16.row.col.f16.f16.f16.f16 " \
                 "{%0,%1}, {%2,%3,%4,%5}, {%6,%7}, {%0,%1};" \
                 : "+r"((d)[0]), "+r"((d)[1]) \
                 : "r"(a0), "r"(a1), "r"(a2), "r"(a3), "r"(b0), "r"(b1))

#define CP_ASYNC16(dst, src) \
    asm volatile("cp.async.cg.shared.global [%0], [%1], 16;" :: "r"(dst), "l"(src) : "memory")
#define CP_COMMIT()  asm volatile("cp.async.commit_group;" ::: "memory")
#define CP_WAIT0()   asm volatile("cp.async.wait_group 0;" ::: "memory")

// ===================== prep: pack weights fp16, K-major, pre-swizzled =====================
// Stage layout: 256 rows x 256B; unit cu (0..15) of row stored at
//   row*256 + (((cu&7) ^ (row&7))<<4) + ((cu>>3)<<7).
// Unit cu holds e=0..7 (fp16) of byte position k = it*16 + cu.
// Row n: g=n>>5, r=n&31; g even -> w1, g odd -> w2; channel = (g>>1)*32 + r.
__global__ void pack_weights(const float* __restrict__ w1, const float* __restrict__ w2) {
    uint32_t t = blockIdx.x * 256u + threadIdx.x;   // 0..131071, one 16B unit each
    uint32_t it = t >> 12;                          // 4096 units per 64KB stage
    uint32_t swoff = (t & 4095u) << 4;              // byte offset inside stage
    uint32_t row = swoff >> 8;
    uint32_t inrow = swoff & 255u;
    uint32_t cu = ((((inrow >> 4) & 7u) ^ (row & 7u))) | ((inrow >> 7) << 3);
    uint32_t k = it * 16u + cu;                     // byte position 0..511
    uint32_t g = row >> 5, r = row & 31u;
    const float* w = (g & 1u) ? w2 : w1;
    const float* s = w + ((g >> 1) * 32u + r) * 4096u + k;  // + e*512
    __half2 h0 = __floats2half2_rn(s[0],    s[512]);
    __half2 h1 = __floats2half2_rn(s[1024], s[1536]);
    __half2 h2 = __floats2half2_rn(s[2048], s[2560]);
    __half2 h3 = __floats2half2_rn(s[3072], s[3584]);
    uint4 v;
    v.x = *reinterpret_cast<uint32_t*>(&h0);
    v.y = *reinterpret_cast<uint32_t*>(&h1);
    v.z = *reinterpret_cast<uint32_t*>(&h2);
    v.w = *reinterpret_cast<uint32_t*>(&h3);
    reinterpret_cast<uint4*>(g_Bpack)[t] = v;
}

// ===================== main fused kernel =====================
__global__ __launch_bounds__(THREADS, 1)
void malconv_main(const int* __restrict__ x, const float* __restrict__ emb,
                  const float* __restrict__ b1, const float* __restrict__ b2,
                  float* __restrict__ out) {
    extern __shared__ unsigned char smem_raw[];
    const uint32_t AL = (smem_u32(smem_raw) + 1023u) & ~1023u;
    const uint32_t sE = AL + OFF_EMB;

    const int tid  = threadIdx.x;
    const int wid  = tid >> 5;
    const int lane = tid & 31;
    const int mw   = wid >> 2;           // 0..1  (64 rows each)
    const int nw   = wid & 3;            // 0..3  (64 cols each)
    const int m0   = blockIdx.x * 128;   // global window base

    // --- emb -> smem fp16 (16B per vocab entry: e0..e7) ---
    for (int v = tid; v < 257; v += THREADS) {
        const float4* e4 = reinterpret_cast<const float4*>(emb + v * 8);
        float4 a = e4[0], bq = e4[1];
        __half2 h0 = __floats2half2_rn(a.x, a.y);
        __half2 h1 = __floats2half2_rn(a.z, a.w);
        __half2 h2 = __floats2half2_rn(bq.x, bq.y);
        __half2 h3 = __floats2half2_rn(bq.z, bq.w);
        STS128(sE + v * 16,
               *reinterpret_cast<uint32_t*>(&h0), *reinterpret_cast<uint32_t*>(&h1),
               *reinterpret_cast<uint32_t*>(&h2), *reinterpret_cast<uint32_t*>(&h3));
    }
    __syncthreads();   // emb visible to A-build

    // --- A-build constants: thread builds row bm, units bu0..bu0+7 (one stage = 16 units) ---
    const int bm  = tid >> 1;
    const int bu0 = (tid & 1) * 8;
    const int* xrow = x + (size_t)(m0 + bm) * 512 + bu0;
    const int bmx = bm & 7;

    #define BUILD_A(sA_, xa_, xb_) do {                                                 \
        const int xv_[8] = { (xa_).x, (xa_).y, (xa_).z, (xa_).w,                        \
                             (xb_).x, (xb_).y, (xb_).z, (xb_).w };                      \
        _Pragma("unroll")                                                               \
        for (int q_ = 0; q_ < 8; ++q_) {                                                \
            uint32_t e0, e1, e2, e3;                                                    \
            LDS128(e0, e1, e2, e3, sE + (uint32_t)xv_[q_] * 16);                        \
            int cu_ = bu0 + q_;                                                         \
            uint32_t off_ = (uint32_t)(bm * 256 + (((cu_ & 7) ^ bmx) << 4)              \
                                       + ((cu_ >> 3) << 7));                            \
            STS128((sA_) + off_, e0, e1, e2, e3);                                       \
        }                                                                               \
    } while (0)

    #define ISSUE_B(stage_, buf_) do {                                                  \
        const char* src_ = (const char*)g_Bpack + (size_t)(stage_) * B_BYTES;           \
        uint32_t dst_ = AL + OFF_B + (buf_) * B_BYTES;                                  \
        _Pragma("unroll")                                                               \
        for (int q_ = 0; q_ < 16; ++q_)                                                 \
            CP_ASYNC16(dst_ + (tid + q_ * 256) * 16, src_ + (tid + q_ * 256) * 16);     \
        CP_COMMIT();                                                                    \
    } while (0)

    // --- prologue: B(0) async; A(0) build; x(1) prefetch ---
    ISSUE_B(0, 0);
    {
        int4 xa = *reinterpret_cast<const int4*>(xrow + 0);
        int4 xb = *reinterpret_cast<const int4*>(xrow + 4);
        BUILD_A(AL + OFF_A + 0 * A_BYTES, xa, xb);
    }
    int4 xca = *reinterpret_cast<const int4*>(xrow + 16);
    int4 xcb = *reinterpret_cast<const int4*>(xrow + 20);

    // --- per-thread ldmatrix address constants ---
    const int q4 = lane >> 3;                          // matrix index 0..3
    const int aRowBase = mw * 64 + (lane & 7) + ((q4 & 1) << 3);
    const int aCuHalf  = q4 >> 1;
    const int aXor     = aRowBase & 7;
    const int bRowBase = nw * 64 + (lane & 7) + ((lane >> 4) << 3);
    const int bCuHalf  = (lane >> 3) & 1;
    const int bXor     = bRowBase & 7;

    float acc[4][8][4];        // fp32 master
    uint32_t facc[4][8][2];    // fp16 running accumulators (4 halves each)
    #pragma unroll
    for (int i = 0; i < 4; ++i)
        #pragma unroll
        for (int j = 0; j < 8; ++j) {
            #pragma unroll
            for (int k = 0; k < 4; ++k) acc[i][j][k] = 0.0f;
            facc[i][j][0] = 0u; facc[i][j][1] = 0u;
        }

    #define OFFA(j_) ((uint32_t)(((((j_) * 2 + aCuHalf) & 7) ^ aXor) << 4) + \
                      ((uint32_t)(((j_) * 2 + aCuHalf) >> 3) << 7))
    #define OFFB(j_) ((uint32_t)(((((j_) * 2 + bCuHalf) & 7) ^ bXor) << 4) + \
                      ((uint32_t)(((j_) * 2 + bCuHalf) >> 3) << 7))

    // --- main loop ---
    for (int it = 0; it < NITER; ++it) {
        CP_WAIT0();               // B(it) resident
        __syncthreads();          // A(it) visible; stage it-1 reads all retired

        const int bufc = it & 1;
        const uint32_t sA = AL + OFF_A + bufc * A_BYTES;
        const uint32_t sB = AL + OFF_B + bufc * B_BYTES;
        const int sNew = it + 1;

        #pragma unroll
        for (int j = 0; j < 8; ++j) {
            uint32_t a[4][4];
            const uint32_t oA = OFFA(j);
            #pragma unroll
            for (int mt = 0; mt < 4; ++mt)
                LDSM4(a[mt][0], a[mt][1], a[mt][2], a[mt][3],
                      sA + (uint32_t)(aRowBase + mt * 16) * 256 + oA);

            // spread next-stage work under the MMAs
            if (sNew < NITER) {
                if (j == 0) {
                    ISSUE_B(sNew, sNew & 1);
                } else if (j == 1) {
                    BUILD_A(AL + OFF_A + (sNew & 1) * A_BYTES, xca, xcb);
                } else if (j == 2) {
                    if (sNew + 1 < NITER) {
                        xca = *reinterpret_cast<const int4*>(xrow + (sNew + 1) * 16);
                        xcb = *reinterpret_cast<const int4*>(xrow + (sNew + 1) * 16 + 4);
                    }
                }
            }

            const uint32_t oB = OFFB(j);
            #pragma unroll
            for (int ntp = 0; ntp < 4; ++ntp) {
                uint32_t bb0, bb1, bb2, bb3;
                LDSM4(bb0, bb1, bb2, bb3,
                      sB + (uint32_t)(bRowBase + ntp * 16) * 256 + oB);
                #pragma unroll
                for (int mt = 0; mt < 4; ++mt) {
                    MMA16816H(facc[mt][ntp * 2 + 0],
                              a[mt][0], a[mt][1], a[mt][2], a[mt][3], bb0, bb1);
                    MMA16816H(facc[mt][ntp * 2 + 1],
                              a[mt][0], a[mt][1], a[mt][2], a[mt][3], bb2, bb3);
                }
            }
        }
        if (sNew >= NITER) CP_COMMIT();

        // flush fp16 accumulators into fp32 master every 2 stages
        if ((it & 1) == 1) {
            #pragma unroll
            for (int mt = 0; mt < 4; ++mt)
                #pragma unroll
                for (int nt = 0; nt < 8; ++nt) {
                    float2 f0 = __half22float2(*reinterpret_cast<__half2*>(&facc[mt][nt][0]));
                    float2 f1 = __half22float2(*reinterpret_cast<__half2*>(&facc[mt][nt][1]));
                    acc[mt][nt][0] += f0.x; acc[mt][nt][1] += f0.y;
                    acc[mt][nt][2] += f1.x; acc[mt][nt][3] += f1.y;
                    facc[mt][nt][0] = 0u;   facc[mt][nt][1] = 0u;
                }
        }
    }

    // --- epilogue: gate + per-patch max, all in registers ---
    float2 b1v[4], b2v[4];
    {
        const int cb = nw * 32 + 2 * (lane & 3);
        #pragma unroll
        for (int nt = 0; nt < 4; ++nt) {
            b1v[nt] = __ldg(reinterpret_cast<const float2*>(b1 + cb + nt * 8));
            b2v[nt] = __ldg(reinterpret_cast<const float2*>(b2 + cb + nt * 8));
        }
    }
    const int bidx  = blockIdx.x >> 4;
    const int pbase = (blockIdx.x & 15) * 4 + mw * 2;

    #pragma unroll
    for (int pp = 0; pp < 2; ++pp) {
        float* obase = out + (size_t)bidx * 8192 + (size_t)(pbase + pp) * 128;
        #pragma unroll
        for (int nt = 0; nt < 4; ++nt) {
            float gm[2];
            #pragma unroll
            for (int cc = 0; cc < 2; ++cc) {
                float bb1 = (cc == 0) ? b1v[nt].x : b1v[nt].y;
                float bb2 = (cc == 0) ? b2v[nt].x : b2v[nt].y;
                float g = -1e30f;
                #pragma unroll
                for (int mt = pp * 2; mt < pp * 2 + 2; ++mt) {
                    #pragma unroll
                    for (int rh = 0; rh < 2; ++rh) {
                        float c1v = acc[mt][nt][cc + rh * 2] + bb1;
                        float c2v = acc[mt][nt + 4][cc + rh * 2] + bb2;
                        float s = __expf(-c2v);
                        g = fmaxf(g, c1v * __frcp_rn(1.0f + s));
                    }
                }
                #pragma unroll
                for (int off = 4; off <= 16; off <<= 1)
                    g = fmaxf(g, __shfl_xor_sync(0xFFFFFFFFu, g, off));
                gm[cc] = g;
            }
            if ((lane >> 2) == 0) {
                const int ch = nw * 32 + nt * 8 + 2 * (lane & 3);
                *reinterpret_cast<float2*>(obase + ch) = make_float2(gm[0], gm[1]);
            }
        }
    }
}

// ===================== launch =====================
extern "C" void kernel_launch(void* const* d_in, const int* in_sizes, int n_in,
                              void* d_out, int out_size) {
    const int*   x   = (const int*)d_in[0];
    const float* emb = (const float*)d_in[1];
    const float* w1  = (const float*)d_in[2];
    const float* b1  = (const float*)d_in[3];
    const float* w2  = (const float*)d_in[4];
    const float* b2  = (const float*)d_in[5];
    float* out = (float*)d_out;

    cudaFuncSetAttribute(malconv_main, cudaFuncAttributeMaxDynamicSharedMemorySize, SMEM_ALLOC);

    pack_weights<<<512, 256>>>(w1, w2);
    malconv_main<<<128, THREADS, SMEM_ALLOC>>>(x, emb, b1, b2, out);
}

// round 7
// speedup vs baseline: 1.1224x; 1.0897x over previous
#include <cuda_runtime.h>
#include <cuda_fp16.h>
#include <stdint.h>

// ===================== problem dims =====================
// B=8, T=1M, V=257, E=8, C=128, K=S=512, N=64 patches
// GEMM: M=16384 windows, N=256 (c1||c2 interleaved by 32-ch groups), K=4096
// CTA: 128 windows (4 patches, one batch), 256 threads / 8 warps (2 Mwarps x 4 Nwarps)
// Warp tile 64x64, fp32 acc. K-stage = 128 halves (16 byte-positions).
// B operand: pre-packed per-lane fragment order in GMEM, ld.global.cg -> regs (no smem).

#define THREADS    256
#define NITER      32            // K stages of 128 halves (= 16 byte positions)

// smem offsets from 1024-aligned base
#define A_BYTES    32768         // 128 rows x 256B
#define OFF_A      0                         // 2 buffers
#define OFF_EMB    (2 * A_BYTES)             // 65536; emb fp16: 257 * 16B
#define SMEM_ALLOC (OFF_EMB + 4128 + 1024)   // ~70KB

// B fragments: [stage 0..31][j 0..7][nw 0..3][ntp 0..3][lane 0..31][16B] = 2 MB
__device__ __align__(16) unsigned char g_Bfrag[32 * 8 * 4 * 4 * 32 * 16];

// ===================== helpers =====================
static __device__ __forceinline__ uint32_t smem_u32(const void* p) {
    uint32_t a;
    asm("{ .reg .u64 t; cvta.to.shared.u64 t, %1; cvt.u32.u64 %0, t; }" : "=r"(a) : "l"(p));
    return a;
}

#define STS128(addr, r0, r1, r2, r3) \
    asm volatile("st.shared.v4.b32 [%0], {%1,%2,%3,%4};" :: "r"(addr), "r"(r0), "r"(r1), "r"(r2), "r"(r3) : "memory")
#define LDS128(r0, r1, r2, r3, addr) \
    asm volatile("ld.shared.v4.b32 {%0,%1,%2,%3}, [%4];" : "=r"(r0), "=r"(r1), "=r"(r2), "=r"(r3) : "r"(addr))

#define LDSM4(r0, r1, r2, r3, addr) \
    asm volatile("ldmatrix.sync.aligned.m8n8.x4.shared.b16 {%0,%1,%2,%3}, [%4];" \
                 : "=r"(r0), "=r"(r1), "=r"(r2), "=r"(r3) : "r"(addr))

#define MMA16816(d, a0, a1, a2, a3, b0, b1) \
    asm volatile("mma.sync.aligned.m16n8k16.row.col.f32.f16.f16.f32 " \
                 "{%0,%1,%2,%3}, {%4,%5,%6,%7}, {%8,%9}, {%0,%1,%2,%3};" \
                 : "+f"((d)[0]), "+f"((d)[1]), "+f"((d)[2]), "+f"((d)[3]) \
                 : "r"(a0), "r"(a1), "r"(a2), "r"(a3), "r"(b0), "r"(b1))

// L2-only 16B load (keeps B traffic off the L1/smem crossbar)
#define LDG128CG(v, ptr) \
    asm volatile("ld.global.cg.v4.u32 {%0,%1,%2,%3}, [%4];" \
                 : "=r"((v).x), "=r"((v).y), "=r"((v).z), "=r"((v).w) : "l"(ptr))

// ===================== prep: pack B into per-lane MMA fragment order =====================
// For (stage, j, nw, ntp, lane): 16B = {bb0, bb1, bb2, bb3} where
//   n0 = nw*64 + ntp*16 + lane/4 ; n1 = n0 + 8 ; e = (lane%4)*2 ; k = stage*16 + j*2
//   bb0 = B[n0][e,e+1 @ k]  bb1 = B[n0][e,e+1 @ k+1]  bb2 = B[n1][..k]  bb3 = B[n1][..k+1]
// Row n: g=n>>5 (even->w1, odd->w2), channel = (g>>1)*32 + (n&31).
// B[n][e @ k] = w[channel*4096 + e*512 + k] as fp16.
__global__ void pack_weights(const float* __restrict__ w1, const float* __restrict__ w2) {
    uint32_t t = blockIdx.x * 256u + threadIdx.x;   // 0..131071, one 16B chunk each
    uint32_t lane = t & 31u;
    uint32_t ntp  = (t >> 5) & 3u;
    uint32_t nw   = (t >> 7) & 3u;
    uint32_t j    = (t >> 9) & 7u;
    uint32_t st   = t >> 12;
    uint32_t k    = st * 16u + j * 2u;
    uint32_t e    = (lane & 3u) * 2u;
    uint32_t n0   = nw * 64u + ntp * 16u + (lane >> 2);
    uint4 v;
    #pragma unroll
    for (int half = 0; half < 2; ++half) {
        uint32_t n = n0 + half * 8u;
        uint32_t g = n >> 5;
        const float* w = (g & 1u) ? w2 : w1;
        const float* s = w + ((g >> 1) * 32u + (n & 31u)) * 4096u + e * 512u + k;
        __half2 h0 = __floats2half2_rn(s[0], s[512]);       // (e, e+1) @ k
        __half2 h1 = __floats2half2_rn(s[1], s[513]);       // (e, e+1) @ k+1
        if (half == 0) { v.x = *reinterpret_cast<uint32_t*>(&h0);
                         v.y = *reinterpret_cast<uint32_t*>(&h1); }
        else           { v.z = *reinterpret_cast<uint32_t*>(&h0);
                         v.w = *reinterpret_cast<uint32_t*>(&h1); }
    }
    reinterpret_cast<uint4*>(g_Bfrag)[t] = v;
}

// ===================== main fused kernel =====================
__global__ __launch_bounds__(THREADS, 1)
void malconv_main(const int* __restrict__ x, const float* __restrict__ emb,
                  const float* __restrict__ b1, const float* __restrict__ b2,
                  float* __restrict__ out) {
    extern __shared__ unsigned char smem_raw[];
    const uint32_t AL = (smem_u32(smem_raw) + 1023u) & ~1023u;
    const uint32_t sE = AL + OFF_EMB;

    const int tid  = threadIdx.x;
    const int wid  = tid >> 5;
    const int lane = tid & 31;
    const int mw   = wid >> 2;           // 0..1  (64 rows each)
    const int nw   = wid & 3;            // 0..3  (64 cols each)
    const int m0   = blockIdx.x * 128;   // global window base

    // --- emb -> smem fp16 (16B per vocab entry: e0..e7) ---
    for (int v = tid; v < 257; v += THREADS) {
        const float4* e4 = reinterpret_cast<const float4*>(emb + v * 8);
        float4 a = e4[0], bq = e4[1];
        __half2 h0 = __floats2half2_rn(a.x, a.y);
        __half2 h1 = __floats2half2_rn(a.z, a.w);
        __half2 h2 = __floats2half2_rn(bq.x, bq.y);
        __half2 h3 = __floats2half2_rn(bq.z, bq.w);
        STS128(sE + v * 16,
               *reinterpret_cast<uint32_t*>(&h0), *reinterpret_cast<uint32_t*>(&h1),
               *reinterpret_cast<uint32_t*>(&h2), *reinterpret_cast<uint32_t*>(&h3));
    }
    __syncthreads();   // emb visible to A-build

    // --- A-build constants: thread builds row bm, units bu0..bu0+7 (one stage = 16 units) ---
    const int bm  = tid >> 1;
    const int bu0 = (tid & 1) * 8;
    const int* xrow = x + (size_t)(m0 + bm) * 512 + bu0;
    const int bmx = bm & 7;

    #define BUILD_A(sA_, xa_, xb_) do {                                                 \
        const int xv_[8] = { (xa_).x, (xa_).y, (xa_).z, (xa_).w,                        \
                             (xb_).x, (xb_).y, (xb_).z, (xb_).w };                      \
        _Pragma("unroll")                                                               \
        for (int q_ = 0; q_ < 8; ++q_) {                                                \
            uint32_t e0, e1, e2, e3;                                                    \
            LDS128(e0, e1, e2, e3, sE + (uint32_t)xv_[q_] * 16);                        \
            int cu_ = bu0 + q_;                                                         \
            uint32_t off_ = (uint32_t)(bm * 256 + (((cu_ & 7) ^ bmx) << 4)              \
                                       + ((cu_ >> 3) << 7));                            \
            STS128((sA_) + off_, e0, e1, e2, e3);                                       \
        }                                                                               \
    } while (0)

    // --- prologue: A(0) build; x(1) prefetch ---
    {
        int4 xa = *reinterpret_cast<const int4*>(xrow + 0);
        int4 xb = *reinterpret_cast<const int4*>(xrow + 4);
        BUILD_A(AL + OFF_A + 0 * A_BYTES, xa, xb);
    }
    int4 xca = *reinterpret_cast<const int4*>(xrow + 16);
    int4 xcb = *reinterpret_cast<const int4*>(xrow + 20);

    // --- per-thread ldmatrix address constants (A) ---
    const int q4 = lane >> 3;                          // matrix index 0..3
    const int aRowBase = mw * 64 + (lane & 7) + ((q4 & 1) << 3);
    const int aCuHalf  = q4 >> 1;
    const int aXor     = aRowBase & 7;

    // --- B fragment pointer: one 16B chunk per (jblock, ntp) ---
    const unsigned char* bptr = g_Bfrag + ((size_t)nw * 2048) + (size_t)lane * 16;
    // advances by 8192 per j-block (32 j-blocks total = stage*8 + j)

    float acc[4][8][4];
    #pragma unroll
    for (int i = 0; i < 4; ++i)
        #pragma unroll
        for (int j = 0; j < 8; ++j)
            #pragma unroll
            for (int k = 0; k < 4; ++k) acc[i][j][k] = 0.0f;

    #define OFFA(j_) ((uint32_t)(((((j_) * 2 + aCuHalf) & 7) ^ aXor) << 4) + \
                      ((uint32_t)(((j_) * 2 + aCuHalf) >> 3) << 7))

    // B register double buffer (prefetched one j-block ahead, continuous across stages)
    uint4 bf[2][4];
    #pragma unroll
    for (int q = 0; q < 4; ++q) LDG128CG(bf[0][q], bptr + q * 512);   // jblock 0

    // --- main loop ---
    for (int it = 0; it < NITER; ++it) {
        __syncthreads();          // A(it) visible; stage it-1 A reads all retired

        const uint32_t sA = AL + OFF_A + (it & 1) * A_BYTES;
        const int sNew = it + 1;

        #pragma unroll
        for (int j = 0; j < 8; ++j) {
            const int cb = j & 1;
            const int nb = cb ^ 1;

            // A fragments for this j
            uint32_t a[4][4];
            const uint32_t oA = OFFA(j);
            #pragma unroll
            for (int mt = 0; mt < 4; ++mt)
                LDSM4(a[mt][0], a[mt][1], a[mt][2], a[mt][3],
                      sA + (uint32_t)(aRowBase + mt * 16) * 256 + oA);

            // prefetch next j-block's B fragments (clamped at the end)
            {
                int nj = it * 8 + j + 1;
                if (nj > 255) nj = 255;
                const unsigned char* np = bptr + (size_t)nj * 8192;
                #pragma unroll
                for (int q = 0; q < 4; ++q) LDG128CG(bf[nb][q], np + q * 512);
            }

            // spread next-stage A work under the MMAs
            if (sNew < NITER) {
                if (j == 1) {
                    BUILD_A(AL + OFF_A + (sNew & 1) * A_BYTES, xca, xcb);
                } else if (j == 2) {
                    if (sNew + 1 < NITER) {
                        xca = *reinterpret_cast<const int4*>(xrow + (sNew + 1) * 16);
                        xcb = *reinterpret_cast<const int4*>(xrow + (sNew + 1) * 16 + 4);
                    }
                }
            }

            // 32 MMAs
            #pragma unroll
            for (int ntp = 0; ntp < 4; ++ntp) {
                const uint4 bq = bf[cb][ntp];
                #pragma unroll
                for (int mt = 0; mt < 4; ++mt) {
                    MMA16816(acc[mt][ntp * 2 + 0], a[mt][0], a[mt][1], a[mt][2], a[mt][3], bq.x, bq.y);
                    MMA16816(acc[mt][ntp * 2 + 1], a[mt][0], a[mt][1], a[mt][2], a[mt][3], bq.z, bq.w);
                }
            }
        }
    }

    // --- epilogue: gate + per-patch max, all in registers ---
    float2 b1v[4], b2v[4];
    {
        const int cb = nw * 32 + 2 * (lane & 3);
        #pragma unroll
        for (int nt = 0; nt < 4; ++nt) {
            b1v[nt] = __ldg(reinterpret_cast<const float2*>(b1 + cb + nt * 8));
            b2v[nt] = __ldg(reinterpret_cast<const float2*>(b2 + cb + nt * 8));
        }
    }
    const int bidx  = blockIdx.x >> 4;
    const int pbase = (blockIdx.x & 15) * 4 + mw * 2;

    #pragma unroll
    for (int pp = 0; pp < 2; ++pp) {
        float* obase = out + (size_t)bidx * 8192 + (size_t)(pbase + pp) * 128;
        #pragma unroll
        for (int nt = 0; nt < 4; ++nt) {
            float gm[2];
            #pragma unroll
            for (int cc = 0; cc < 2; ++cc) {
                float bb1 = (cc == 0) ? b1v[nt].x : b1v[nt].y;
                float bb2 = (cc == 0) ? b2v[nt].x : b2v[nt].y;
                float g = -1e30f;
                #pragma unroll
                for (int mt = pp * 2; mt < pp * 2 + 2; ++mt) {
                    #pragma unroll
                    for (int rh = 0; rh < 2; ++rh) {
                        float c1v = acc[mt][nt][cc + rh * 2] + bb1;
                        float c2v = acc[mt][nt + 4][cc + rh * 2] + bb2;
                        float s = __expf(-c2v);
                        g = fmaxf(g, c1v * __frcp_rn(1.0f + s));
                    }
                }
                #pragma unroll
                for (int off = 4; off <= 16; off <<= 1)
                    g = fmaxf(g, __shfl_xor_sync(0xFFFFFFFFu, g, off));
                gm[cc] = g;
            }
            if ((lane >> 2) == 0) {
                const int ch = nw * 32 + nt * 8 + 2 * (lane & 3);
                *reinterpret_cast<float2*>(obase + ch) = make_float2(gm[0], gm[1]);
            }
        }
    }
}

// ===================== launch =====================
extern "C" void kernel_launch(void* const* d_in, const int* in_sizes, int n_in,
                              void* d_out, int out_size) {
    const int*   x   = (const int*)d_in[0];
    const float* emb = (const float*)d_in[1];
    const float* w1  = (const float*)d_in[2];
    const float* b1  = (const float*)d_in[3];
    const float* w2  = (const float*)d_in[4];
    const float* b2  = (const float*)d_in[5];
    float* out = (float*)d_out;

    cudaFuncSetAttribute(malconv_main, cudaFuncAttributeMaxDynamicSharedMemorySize, SMEM_ALLOC);

    pack_weights<<<512, 256>>>(w1, w2);
    malconv_main<<<128, THREADS, SMEM_ALLOC>>>(x, emb, b1, b2, out);
}

// round 9
// speedup vs baseline: 1.1250x; 1.0023x over previous
#include <cuda_runtime.h>
#include <cuda_fp16.h>
#include <stdint.h>

// ===================== problem dims =====================
// B=8, T=1M, V=257, E=8, C=128, K=S=512, N=64 patches
// GEMM: M=16384 windows, N=256 (c1||c2 interleaved by 32-ch groups), K=4096
// CTA: 128 windows x 128 N-cols, 128 threads / 4 warps (2 Mwarps x 2 Nwarps)
// Warp tile 64x64, fp32 acc. Grid = 128 M-tiles x 2 N-halves = 256 CTAs, 2 CTAs/SM.
// B operand: pre-packed per-lane fragment order in GMEM, ld.global.cg -> regs (no smem).

#define THREADS    128
#define NITER      32            // K stages of 128 halves (= 16 byte positions)

// smem offsets from 1024-aligned base
#define A_BYTES    32768         // 128 rows x 256B
#define OFF_A      0                         // 2 buffers
#define OFF_EMB    (2 * A_BYTES)             // 65536; emb fp16: 257 * 16B
#define SMEM_ALLOC (OFF_EMB + 4128 + 1024)   // 70688 (x2 CTAs = 141KB < 228KB)

// B fragments: [stage 0..31][j 0..7][nwg 0..3][ntp 0..3][lane 0..31][16B] = 2 MB
__device__ __align__(16) unsigned char g_Bfrag[32 * 8 * 4 * 4 * 32 * 16];

// ===================== helpers =====================
static __device__ __forceinline__ uint32_t smem_u32(const void* p) {
    uint32_t a;
    asm("{ .reg .u64 t; cvta.to.shared.u64 t, %1; cvt.u32.u64 %0, t; }" : "=r"(a) : "l"(p));
    return a;
}

#define STS128(addr, r0, r1, r2, r3) \
    asm volatile("st.shared.v4.b32 [%0], {%1,%2,%3,%4};" :: "r"(addr), "r"(r0), "r"(r1), "r"(r2), "r"(r3) : "memory")
#define LDS128(r0, r1, r2, r3, addr) \
    asm volatile("ld.shared.v4.b32 {%0,%1,%2,%3}, [%4];" : "=r"(r0), "=r"(r1), "=r"(r2), "=r"(r3) : "r"(addr))

#define LDSM4(r0, r1, r2, r3, addr) \
    asm volatile("ldmatrix.sync.aligned.m8n8.x4.shared.b16 {%0,%1,%2,%3}, [%4];" \
                 : "=r"(r0), "=r"(r1), "=r"(r2), "=r"(r3) : "r"(addr))

#define MMA16816(d, a0, a1, a2, a3, b0, b1) \
    asm volatile("mma.sync.aligned.m16n8k16.row.col.f32.f16.f16.f32 " \
                 "{%0,%1,%2,%3}, {%4,%5,%6,%7}, {%8,%9}, {%0,%1,%2,%3};" \
                 : "+f"((d)[0]), "+f"((d)[1]), "+f"((d)[2]), "+f"((d)[3]) \
                 : "r"(a0), "r"(a1), "r"(a2), "r"(a3), "r"(b0), "r"(b1))

// L2-only 16B load (keeps B data out of L1 cache lines; still uses L1tex port)
#define LDG128CG(v, ptr) \
    asm volatile("ld.global.cg.v4.u32 {%0,%1,%2,%3}, [%4];" \
                 : "=r"((v).x), "=r"((v).y), "=r"((v).z), "=r"((v).w) : "l"(ptr))

// ===================== prep: pack B into per-lane MMA fragment order =====================
// For (stage, j, nwg, ntp, lane): 16B = {bb0, bb1, bb2, bb3} where
//   n0 = nwg*64 + ntp*16 + lane/4 ; n1 = n0 + 8 ; e = (lane%4)*2 ; k = stage*16 + j*2
// Row n: g=n>>5 (even->w1, odd->w2), channel = (g>>1)*32 + (n&31).
__global__ void pack_weights(const float* __restrict__ w1, const float* __restrict__ w2) {
    uint32_t t = blockIdx.x * 256u + threadIdx.x;   // 0..131071, one 16B chunk each
    uint32_t lane = t & 31u;
    uint32_t ntp  = (t >> 5) & 3u;
    uint32_t nwg  = (t >> 7) & 3u;
    uint32_t j    = (t >> 9) & 7u;
    uint32_t st   = t >> 12;
    uint32_t k    = st * 16u + j * 2u;
    uint32_t e    = (lane & 3u) * 2u;
    uint32_t n0   = nwg * 64u + ntp * 16u + (lane >> 2);
    uint4 v;
    #pragma unroll
    for (int half = 0; half < 2; ++half) {
        uint32_t n = n0 + half * 8u;
        uint32_t g = n >> 5;
        const float* w = (g & 1u) ? w2 : w1;
        const float* s = w + ((g >> 1) * 32u + (n & 31u)) * 4096u + e * 512u + k;
        __half2 h0 = __floats2half2_rn(s[0], s[512]);       // (e, e+1) @ k
        __half2 h1 = __floats2half2_rn(s[1], s[513]);       // (e, e+1) @ k+1
        if (half == 0) { v.x = *reinterpret_cast<uint32_t*>(&h0);
                         v.y = *reinterpret_cast<uint32_t*>(&h1); }
        else           { v.z = *reinterpret_cast<uint32_t*>(&h0);
                         v.w = *reinterpret_cast<uint32_t*>(&h1); }
    }
    reinterpret_cast<uint4*>(g_Bfrag)[t] = v;
}

// ===================== main fused kernel =====================
__global__ __launch_bounds__(THREADS, 2)
void malconv_main(const int* __restrict__ x, const float* __restrict__ emb,
                  const float* __restrict__ b1, const float* __restrict__ b2,
                  float* __restrict__ out) {
    extern __shared__ unsigned char smem_raw[];
    const uint32_t AL = (smem_u32(smem_raw) + 1023u) & ~1023u;
    const uint32_t sE = AL + OFF_EMB;

    const int tid   = threadIdx.x;
    const int wid   = tid >> 5;
    const int lane  = tid & 31;
    const int mw    = wid >> 1;            // 0..1  (64 rows each)
    const int nwp   = wid & 1;             // 0..1  (64 cols each within half)
    const int ctam  = blockIdx.x >> 1;     // 0..127 M-tile
    const int nhalf = blockIdx.x & 1;      // 0..1  N-half
    const int nwg   = nhalf * 2 + nwp;     // 0..3  global 64-col group
    const int m0    = ctam * 128;          // global window base

    // --- emb -> smem fp16 (16B per vocab entry: e0..e7) ---
    for (int v = tid; v < 257; v += THREADS) {
        const float4* e4 = reinterpret_cast<const float4*>(emb + v * 8);
        float4 a = e4[0], bq = e4[1];
        __half2 h0 = __floats2half2_rn(a.x, a.y);
        __half2 h1 = __floats2half2_rn(a.z, a.w);
        __half2 h2 = __floats2half2_rn(bq.x, bq.y);
        __half2 h3 = __floats2half2_rn(bq.z, bq.w);
        STS128(sE + v * 16,
               *reinterpret_cast<uint32_t*>(&h0), *reinterpret_cast<uint32_t*>(&h1),
               *reinterpret_cast<uint32_t*>(&h2), *reinterpret_cast<uint32_t*>(&h3));
    }
    __syncthreads();   // emb visible to A-build

    // --- A-build: thread builds row bm (= tid), all 16 units of the stage in 2 halves ---
    const int bm = tid;
    const int* xrow = x + (size_t)(m0 + bm) * 512;
    const int bmx = bm & 7;

    // build units q0..q0+7 of this thread's row from 8 x-values
    #define BUILD_A8(sA_, xa_, xb_, q0_) do {                                           \
        const int xv_[8] = { (xa_).x, (xa_).y, (xa_).z, (xa_).w,                        \
                             (xb_).x, (xb_).y, (xb_).z, (xb_).w };                      \
        _Pragma("unroll")                                                               \
        for (int q_ = 0; q_ < 8; ++q_) {                                                \
            uint32_t e0, e1, e2, e3;                                                    \
            LDS128(e0, e1, e2, e3, sE + (uint32_t)xv_[q_] * 16);                        \
            int cu_ = (q0_) + q_;                                                       \
            uint32_t off_ = (uint32_t)(bm * 256 + (((cu_ & 7) ^ bmx) << 4)              \
                                       + ((cu_ >> 3) << 7));                            \
            STS128((sA_) + off_, e0, e1, e2, e3);                                       \
        }                                                                               \
    } while (0)

    // --- prologue: A(0) build; x(1) prefetch ---
    {
        int4 xa = *reinterpret_cast<const int4*>(xrow + 0);
        int4 xb = *reinterpret_cast<const int4*>(xrow + 4);
        int4 xc = *reinterpret_cast<const int4*>(xrow + 8);
        int4 xd = *reinterpret_cast<const int4*>(xrow + 12);
        BUILD_A8(AL + OFF_A, xa, xb, 0);
        BUILD_A8(AL + OFF_A, xc, xd, 8);
    }
    int4 xca = *reinterpret_cast<const int4*>(xrow + 16);
    int4 xcb = *reinterpret_cast<const int4*>(xrow + 20);
    int4 xcc = *reinterpret_cast<const int4*>(xrow + 24);
    int4 xcd = *reinterpret_cast<const int4*>(xrow + 28);

    // --- per-thread ldmatrix address constants (A) ---
    const int q4 = lane >> 3;                          // matrix index 0..3
    const int aRowBase = mw * 64 + (lane & 7) + ((q4 & 1) << 3);
    const int aCuHalf  = q4 >> 1;
    const int aXor     = aRowBase & 7;

    // --- B fragment pointer: one 16B chunk per (jblock, ntp) ---
    const unsigned char* bptr = g_Bfrag + ((size_t)nwg * 2048) + (size_t)lane * 16;

    float acc[4][8][4];
    #pragma unroll
    for (int i = 0; i < 4; ++i)
        #pragma unroll
        for (int j = 0; j < 8; ++j)
            #pragma unroll
            for (int k = 0; k < 4; ++k) acc[i][j][k] = 0.0f;

    #define OFFA(j_) ((uint32_t)(((((j_) * 2 + aCuHalf) & 7) ^ aXor) << 4) + \
                      ((uint32_t)(((j_) * 2 + aCuHalf) >> 3) << 7))

    // B register double buffer (prefetched one j-block ahead, continuous across stages)
    uint4 bf[2][4];
    #pragma unroll
    for (int q = 0; q < 4; ++q) LDG128CG(bf[0][q], bptr + q * 512);   // jblock 0

    // --- main loop ---
    for (int it = 0; it < NITER; ++it) {
        __syncthreads();          // A(it) visible; stage it-1 A reads all retired

        const uint32_t sA = AL + OFF_A + (it & 1) * A_BYTES;
        const int sNew = it + 1;
        const uint32_t sAn = AL + OFF_A + (sNew & 1) * A_BYTES;

        #pragma unroll
        for (int j = 0; j < 8; ++j) {
            const int cb = j & 1;
            const int nb = cb ^ 1;

            // A fragments for this j
            uint32_t a[4][4];
            const uint32_t oA = OFFA(j);
            #pragma unroll
            for (int mt = 0; mt < 4; ++mt)
                LDSM4(a[mt][0], a[mt][1], a[mt][2], a[mt][3],
                      sA + (uint32_t)(aRowBase + mt * 16) * 256 + oA);

            // prefetch next j-block's B fragments (clamped at the end)
            {
                int nj = it * 8 + j + 1;
                if (nj > 255) nj = 255;
                const unsigned char* np = bptr + (size_t)nj * 8192;
                #pragma unroll
                for (int q = 0; q < 4; ++q) LDG128CG(bf[nb][q], np + q * 512);
            }

            // spread next-stage A work under the MMAs
            if (sNew < NITER) {
                if (j == 1) {
                    BUILD_A8(sAn, xca, xcb, 0);
                } else if (j == 2) {
                    BUILD_A8(sAn, xcc, xcd, 8);
                } else if (j == 3) {
                    if (sNew + 1 < NITER) {
                        xca = *reinterpret_cast<const int4*>(xrow + (sNew + 1) * 16);
                        xcb = *reinterpret_cast<const int4*>(xrow + (sNew + 1) * 16 + 4);
                        xcc = *reinterpret_cast<const int4*>(xrow + (sNew + 1) * 16 + 8);
                        xcd = *reinterpret_cast<const int4*>(xrow + (sNew + 1) * 16 + 12);
                    }
                }
            }

            // 32 MMAs
            #pragma unroll
            for (int ntp = 0; ntp < 4; ++ntp) {
                const uint4 bq = bf[cb][ntp];
                #pragma unroll
                for (int mt = 0; mt < 4; ++mt) {
                    MMA16816(acc[mt][ntp * 2 + 0], a[mt][0], a[mt][1], a[mt][2], a[mt][3], bq.x, bq.y);
                    MMA16816(acc[mt][ntp * 2 + 1], a[mt][0], a[mt][1], a[mt][2], a[mt][3], bq.z, bq.w);
                }
            }
        }
    }

    // --- epilogue: gate + per-patch max, all in registers ---
    // warp rows: mw*64 + mt*16 + (l/4) + {0,8}; patches: mt{0,1} -> patch0, mt{2,3} -> patch1
    // cols: nt 0..3 = c1 channels nwg*32 + nt*8 + 2*(l%4)+cc ; nt+4 = matching c2
    float2 b1v[4], b2v[4];
    {
        const int cb = nwg * 32 + 2 * (lane & 3);
        #pragma unroll
        for (int nt = 0; nt < 4; ++nt) {
            b1v[nt] = __ldg(reinterpret_cast<const float2*>(b1 + cb + nt * 8));
            b2v[nt] = __ldg(reinterpret_cast<const float2*>(b2 + cb + nt * 8));
        }
    }
    const int bidx  = ctam >> 4;                       // batch
    const int pbase = (ctam & 15) * 4 + mw * 2;        // patch base within batch

    #pragma unroll
    for (int pp = 0; pp < 2; ++pp) {
        float* obase = out + (size_t)bidx * 8192 + (size_t)(pbase + pp) * 128;
        #pragma unroll
        for (int nt = 0; nt < 4; ++nt) {
            float gm[2];
            #pragma unroll
            for (int cc = 0; cc < 2; ++cc) {
                float bb1 = (cc == 0) ? b1v[nt].x : b1v[nt].y;
                float bb2 = (cc == 0) ? b2v[nt].x : b2v[nt].y;
                float g = -1e30f;
                #pragma unroll
                for (int mt = pp * 2; mt < pp * 2 + 2; ++mt) {
                    #pragma unroll
                    for (int rh = 0; rh < 2; ++rh) {
                        float c1v = acc[mt][nt][cc + rh * 2] + bb1;
                        float c2v = acc[mt][nt + 4][cc + rh * 2] + bb2;
                        float s = __expf(-c2v);
                        g = fmaxf(g, c1v * __frcp_rn(1.0f + s));
                    }
                }
                #pragma unroll
                for (int off = 4; off <= 16; off <<= 1)
                    g = fmaxf(g, __shfl_xor_sync(0xFFFFFFFFu, g, off));
                gm[cc] = g;
            }
            if ((lane >> 2) == 0) {
                const int ch = nwg * 32 + nt * 8 + 2 * (lane & 3);
                *reinterpret_cast<float2*>(obase + ch) = make_float2(gm[0], gm[1]);
            }
        }
    }
}

// ===================== launch =====================
extern "C" void kernel_launch(void* const* d_in, const int* in_sizes, int n_in,
                              void* d_out, int out_size) {
    const int*   x   = (const int*)d_in[0];
    const float* emb = (const float*)d_in[1];
    const float* w1  = (const float*)d_in[2];
    const float* b1  = (const float*)d_in[3];
    const float* w2  = (const float*)d_in[4];
    const float* b2  = (const float*)d_in[5];
    float* out = (float*)d_out;

    cudaFuncSetAttribute(malconv_main, cudaFuncAttributeMaxDynamicSharedMemorySize, SMEM_ALLOC);

    pack_weights<<<512, 256>>>(w1, w2);
    malconv_main<<<256, THREADS, SMEM_ALLOC>>>(x, emb, b1, b2, out);
}